// round 4
// baseline (speedup 1.0000x reference)
#include <cuda_runtime.h>
#include <cuda_bf16.h>
#include <math.h>

// Problem constants
#define BB 8
#define NN 512
#define CC 37
#define CF 36        // foreground classes
#define DD 2048
#define SCORE_THR 0.1f
#define NMS_THR 0.4f

// Output layout (float32, reference return order, flattened+concatenated):
//   cls_dets  [B, CF, N, 5]  : 737280 floats, offset 0
//   kept_feats[B, N, D]      : 8388608 floats, offset 737280
//   keep      [B, CF, N]     : 147456 floats (0/1), offset 9125888
#define OUT_DETS_OFF   0
#define OUT_FEATS_OFF  737280
#define OUT_KEEP_OFF   9125888

#define FULLMASK 0xFFFFFFFFu

// float -> order-preserving unsigned (finite floats)
__device__ __forceinline__ unsigned f2ord(float f) {
    unsigned u = __float_as_uint(f);
    return (u & 0x80000000u) ? ~u : (u | 0x80000000u);
}

// ---------------------------------------------------------------------------
// Kernel 1: fused decode + NMS. One block = one (b, fg-class), 512 threads.
// Valid boxes (score > thr, ~35 expected) are compacted, ranked, decoded into
// shared in sorted order; then WARP 0 alone runs the greedy NMS with shfl
// (no block-wide barriers in the loop).
// ---------------------------------------------------------------------------
__global__ __launch_bounds__(512) void nms_fused_kernel(
    const float* __restrict__ rois,
    const float* __restrict__ bbox_pred,
    const float* __restrict__ scores,
    const float* __restrict__ im_info,
    float* __restrict__ out)
{
    __shared__ unsigned long long keys[NN];           // compacted valid keys
    __shared__ float sx1[NN], sy1[NN], sx2[NN], sy2[NN], sar[NN]; // sorted boxes
    __shared__ int   keepflag[NN];                    // per sorted rank
    __shared__ int   cnt;

    int tid = threadIdx.x;
    int bc  = blockIdx.x;          // b*CF + c
    int c   = bc % CF;             // fg class -> real class c+1
    int b   = bc / CF;

    if (tid == 0) cnt = 0;
    __syncthreads();

    float s = __ldg(&scores[(b * NN + tid) * CC + (c + 1)]);
    bool valid = s > SCORE_THR;

    // key: score desc, tie -> lower original index first (stable argsort)
    unsigned long long mycomp = 0ull;
    if (valid) {
        mycomp = ((unsigned long long)f2ord(s) << 32) | (unsigned)(NN - 1 - tid);
        int pos = atomicAdd(&cnt, 1);
        keys[pos] = mycomp;
    }
    __syncthreads();
    int vc = cnt;

    // valid threads: rank by counting, decode box, store at sorted position
    float mx1 = 0.f, my1 = 0.f, mx2 = 0.f, my2 = 0.f, marea = 0.f;
    int rank = -1;
    if (valid) {
        int r = 0;
        for (int j = 0; j < vc; j++) r += (keys[j] > mycomp);
        rank = r;

        const float* rr = rois + (b * NN + tid) * 5;
        float rx1 = __ldg(rr + 1), ry1 = __ldg(rr + 2);
        float rx2 = __ldg(rr + 3), ry2 = __ldg(rr + 4);
        float w  = rx2 - rx1;
        float h  = ry2 - ry1;
        float cx = rx1 + 0.5f * w;
        float cy = ry1 + 0.5f * h;

        const float* dp = bbox_pred + ((b * NN + tid) * CC + (c + 1)) * 4;
        float d0 = __ldg(dp + 0) * 0.1f;
        float d1 = __ldg(dp + 1) * 0.1f;
        float d2 = __ldg(dp + 2) * 0.2f;
        float d3 = __ldg(dp + 3) * 0.2f;

        float px = d0 * w + cx;
        float py = d1 * h + cy;
        float pw = expf(d2) * w;
        float ph = expf(d3) * h;

        float xmax = __ldg(&im_info[b * 3 + 1]) - 1.0f;
        float ymax = __ldg(&im_info[b * 3 + 0]) - 1.0f;
        mx1 = fminf(fmaxf(px - 0.5f * pw, 0.0f), xmax);
        my1 = fminf(fmaxf(py - 0.5f * ph, 0.0f), ymax);
        mx2 = fminf(fmaxf(px + 0.5f * pw, 0.0f), xmax);
        my2 = fminf(fmaxf(py + 0.5f * ph, 0.0f), ymax);
        marea = (mx2 - mx1) * (my2 - my1);

        sx1[rank] = mx1; sy1[rank] = my1;
        sx2[rank] = mx2; sy2[rank] = my2;
        sar[rank] = marea;
    }
    __syncthreads();

    // ---- warp 0: greedy NMS over sorted prefix, no block barriers ----
    if (tid < 32) {
        int lane = tid;
        unsigned suppbits = 0;   // bit k -> rank (lane + 32k) suppressed
        for (int i = 0; i < vc; i++) {
            int owner = i & 31;
            int ck    = i >> 5;
            unsigned ob = __shfl_sync(FULLMASK, suppbits, owner);
            bool kept = !((ob >> ck) & 1u);
            if (lane == owner) keepflag[i] = kept ? 1 : 0;
            if (kept) {
                float ix1 = sx1[i], iy1 = sy1[i], ix2 = sx2[i], iy2 = sy2[i];
                float ia  = sar[i];
                for (int k = 0; lane + 32 * k < vc; k++) {
                    int j = lane + 32 * k;
                    if (j > i && !((suppbits >> k) & 1u)) {
                        float lx = fmaxf(sx1[j], ix1);
                        float ly = fmaxf(sy1[j], iy1);
                        float rx = fminf(sx2[j], ix2);
                        float ry = fminf(sy2[j], iy2);
                        float iw = fmaxf(rx - lx, 0.0f);
                        float ih = fmaxf(ry - ly, 0.0f);
                        float inter = iw * ih;
                        float iou = inter / (sar[j] + ia - inter + 1e-9f);
                        if (iou > NMS_THR) suppbits |= (1u << k);
                    }
                }
            }
        }
    }
    __syncthreads();

    bool k = valid && (keepflag[rank] != 0);

    size_t det_base = (size_t)OUT_DETS_OFF + ((size_t)bc * NN + tid) * 5;
    if (k) {
        out[det_base + 0] = mx1;
        out[det_base + 1] = my1;
        out[det_base + 2] = mx2;
        out[det_base + 3] = my2;
        out[det_base + 4] = s;
    } else {
        out[det_base + 0] = 0.0f;
        out[det_base + 1] = 0.0f;
        out[det_base + 2] = 0.0f;
        out[det_base + 3] = 0.0f;
        out[det_base + 4] = 0.0f;
    }
    out[(size_t)OUT_KEEP_OFF + (size_t)bc * NN + tid] = k ? 1.0f : 0.0f;
}

// ---------------------------------------------------------------------------
// Kernel 2: masked feature copy. Warp-per-row, no block barriers.
// 256-thread blocks = 8 independent warps; grid 512 covers 4096 rows.
// ---------------------------------------------------------------------------
__global__ __launch_bounds__(256) void feats_kernel(
    const float4* __restrict__ feats,
    float* __restrict__ out)
{
    int row  = blockIdx.x * 8 + (threadIdx.x >> 5);   // b*NN + n, 0..4095
    int lane = threadIdx.x & 31;
    int b = row >> 9;
    int n = row & (NN - 1);

    // keep[b, cls, n]: lane covers cls = lane and cls = lane + 32 (lane < 4)
    const float* kb = out + (size_t)OUT_KEEP_OFF + (size_t)b * CF * NN + n;
    float k0 = kb[(size_t)lane * NN];
    float k1 = (lane < CF - 32) ? kb[(size_t)(lane + 32) * NN] : 0.0f;
    unsigned any = __ballot_sync(FULLMASK, (k0 != 0.0f) || (k1 != 0.0f));

    const float4* src = feats + (size_t)row * (DD / 4);
    float4* dst = (float4*)(out + OUT_FEATS_OFF) + (size_t)row * (DD / 4);

    if (any) {
        #pragma unroll
        for (int i = 0; i < DD / 4 / 32; i++)     // 16 float4 per lane
            dst[lane + 32 * i] = __ldg(&src[lane + 32 * i]);
    } else {
        float4 z = make_float4(0.f, 0.f, 0.f, 0.f);
        #pragma unroll
        for (int i = 0; i < DD / 4 / 32; i++)
            dst[lane + 32 * i] = z;
    }
}

extern "C" void kernel_launch(void* const* d_in, const int* in_sizes, int n_in,
                              void* d_out, int out_size) {
    const float* rois      = (const float*)d_in[0];
    const float* bbox_pred = (const float*)d_in[1];
    const float* scores    = (const float*)d_in[2];
    const float* im_info   = (const float*)d_in[3];
    const float* feats     = (const float*)d_in[4];
    float* out = (float*)d_out;

    nms_fused_kernel<<<BB * CF, 512>>>(rois, bbox_pred, scores, im_info, out);
    feats_kernel<<<BB * NN / 8, 256>>>((const float4*)feats, out);
}

// round 5
// speedup vs baseline: 1.4112x; 1.4112x over previous
#include <cuda_runtime.h>
#include <cuda_bf16.h>
#include <math.h>

// Problem constants
#define BB 8
#define NN 512
#define CC 37
#define CF 36        // foreground classes
#define DD 2048
#define SCORE_THR 0.1f
#define NMS_THR 0.4f

// Output layout (float32, reference return order, flattened+concatenated):
//   cls_dets  [B, CF, N, 5]  : 737280 floats, offset 0
//   kept_feats[B, N, D]      : 8388608 floats, offset 737280
//   keep      [B, CF, N]     : 147456 floats (0/1), offset 9125888
#define OUT_DETS_OFF   0
#define OUT_FEATS_OFF  737280
#define OUT_KEEP_OFF   9125888

#define FULLMASK 0xFFFFFFFFu

// Per-roi any-class-kept flag. Zero-initialized at module load (.bss); the
// feats kernel re-zeroes each slot after consuming it, so every kernel_launch
// call observes all-zero entry state. Deterministic across graph replays.
__device__ int g_anykeep[BB * NN];

// float -> order-preserving unsigned (finite floats)
__device__ __forceinline__ unsigned f2ord(float f) {
    unsigned u = __float_as_uint(f);
    return (u & 0x80000000u) ? ~u : (u | 0x80000000u);
}

// ---------------------------------------------------------------------------
// Kernel 1: fused decode + NMS. One block = one (b, fg-class), 512 threads.
// Invalid threads (score <= thr, ~93%) write their zero outputs and EXIT
// before the greedy loop, so loop barriers involve only ~vc threads.
// ---------------------------------------------------------------------------
__global__ __launch_bounds__(512) void nms_fused_kernel(
    const float* __restrict__ rois,
    const float* __restrict__ bbox_pred,
    const float* __restrict__ scores,
    const float* __restrict__ im_info,
    float* __restrict__ out)
{
    __shared__ unsigned long long keys[NN];           // compacted valid keys
    __shared__ float sx1[NN], sy1[NN], sx2[NN], sy2[NN], sar[NN]; // sorted boxes
    __shared__ int   keepflag[NN];                    // per sorted rank
    __shared__ int   cnt;

    int tid = threadIdx.x;
    int bc  = blockIdx.x;          // b*CF + c
    int c   = bc % CF;             // fg class -> real class c+1
    int b   = bc / CF;

    if (tid == 0) cnt = 0;
    __syncthreads();

    float s = __ldg(&scores[(b * NN + tid) * CC + (c + 1)]);
    bool valid = s > SCORE_THR;

    // key: score desc, tie -> lower original index first (stable argsort)
    unsigned long long mycomp = 0ull;
    if (valid) {
        mycomp = ((unsigned long long)f2ord(s) << 32) | (unsigned)(NN - 1 - tid);
        int pos = atomicAdd(&cnt, 1);
        keys[pos] = mycomp;
    }
    __syncthreads();
    int vc = cnt;

    size_t det_base = (size_t)OUT_DETS_OFF + ((size_t)bc * NN + tid) * 5;

    // Invalid threads: outputs are zeros; write and leave. Remaining barriers
    // synchronize only the surviving (valid) threads (sm_70+ semantics).
    if (!valid) {
        out[det_base + 0] = 0.0f;
        out[det_base + 1] = 0.0f;
        out[det_base + 2] = 0.0f;
        out[det_base + 3] = 0.0f;
        out[det_base + 4] = 0.0f;
        out[(size_t)OUT_KEEP_OFF + (size_t)bc * NN + tid] = 0.0f;
        return;
    }

    // rank by counting (stable), decode box, store at sorted position
    int rank = 0;
    for (int j = 0; j < vc; j++) rank += (keys[j] > mycomp);

    const float* rr = rois + (b * NN + tid) * 5;
    float rx1 = __ldg(rr + 1), ry1 = __ldg(rr + 2);
    float rx2 = __ldg(rr + 3), ry2 = __ldg(rr + 4);
    float w  = rx2 - rx1;
    float h  = ry2 - ry1;
    float cx = rx1 + 0.5f * w;
    float cy = ry1 + 0.5f * h;

    const float* dp = bbox_pred + ((b * NN + tid) * CC + (c + 1)) * 4;
    float d0 = __ldg(dp + 0) * 0.1f;
    float d1 = __ldg(dp + 1) * 0.1f;
    float d2 = __ldg(dp + 2) * 0.2f;
    float d3 = __ldg(dp + 3) * 0.2f;

    float px = d0 * w + cx;
    float py = d1 * h + cy;
    float pw = expf(d2) * w;
    float ph = expf(d3) * h;

    float xmax = __ldg(&im_info[b * 3 + 1]) - 1.0f;
    float ymax = __ldg(&im_info[b * 3 + 0]) - 1.0f;
    float mx1 = fminf(fmaxf(px - 0.5f * pw, 0.0f), xmax);
    float my1 = fminf(fmaxf(py - 0.5f * ph, 0.0f), ymax);
    float mx2 = fminf(fmaxf(px + 0.5f * pw, 0.0f), xmax);
    float my2 = fminf(fmaxf(py + 0.5f * ph, 0.0f), ymax);
    float marea = (mx2 - mx1) * (my2 - my1);

    sx1[rank] = mx1; sy1[rank] = my1;
    sx2[rank] = mx2; sy2[rank] = my2;
    sar[rank] = marea;
    __syncthreads();   // valid threads only

    // block-parallel greedy NMS over the sorted valid prefix
    for (int i = 0; i < vc; i++) {
        bool sup = false;
        if (rank < i && keepflag[rank]) {
            float lx = fmaxf(mx1, sx1[i]);
            float ly = fmaxf(my1, sy1[i]);
            float rx = fminf(mx2, sx2[i]);
            float ry = fminf(my2, sy2[i]);
            float iw = fmaxf(rx - lx, 0.0f);
            float ih = fmaxf(ry - ly, 0.0f);
            float inter = iw * ih;
            float iou = inter / (marea + sar[i] - inter + 1e-9f);
            sup = iou > NMS_THR;
        }
        int any = __syncthreads_or((int)sup);
        if (rank == i) keepflag[i] = any ? 0 : 1;
        __syncthreads();
    }

    bool k = (keepflag[rank] != 0);
    if (k) {
        out[det_base + 0] = mx1;
        out[det_base + 1] = my1;
        out[det_base + 2] = mx2;
        out[det_base + 3] = my2;
        out[det_base + 4] = s;
        atomicOr(&g_anykeep[b * NN + tid], 1);
    } else {
        out[det_base + 0] = 0.0f;
        out[det_base + 1] = 0.0f;
        out[det_base + 2] = 0.0f;
        out[det_base + 3] = 0.0f;
        out[det_base + 4] = 0.0f;
    }
    out[(size_t)OUT_KEEP_OFF + (size_t)bc * NN + tid] = k ? 1.0f : 0.0f;
}

// ---------------------------------------------------------------------------
// Kernel 2: masked feature copy. Warp-per-row; mask = ONE broadcast load of
// g_anykeep[row], then lane 0 (sole reader) re-zeroes the slot.
// ---------------------------------------------------------------------------
__global__ __launch_bounds__(256) void feats_kernel(
    const float4* __restrict__ feats,
    float* __restrict__ out)
{
    int row  = blockIdx.x * 8 + (threadIdx.x >> 5);   // b*NN + n, 0..4095
    int lane = threadIdx.x & 31;

    int any = 0;
    if (lane == 0) {
        any = g_anykeep[row];
        if (any) g_anykeep[row] = 0;   // restore zero-invariant for next call
    }
    any = __shfl_sync(FULLMASK, any, 0);

    const float4* src = feats + (size_t)row * (DD / 4);
    float4* dst = (float4*)(out + OUT_FEATS_OFF) + (size_t)row * (DD / 4);

    if (any) {
        #pragma unroll
        for (int i = 0; i < DD / 4 / 32; i++)     // 16 float4 per lane
            dst[lane + 32 * i] = __ldg(&src[lane + 32 * i]);
    } else {
        float4 z = make_float4(0.f, 0.f, 0.f, 0.f);
        #pragma unroll
        for (int i = 0; i < DD / 4 / 32; i++)
            dst[lane + 32 * i] = z;
    }
}

extern "C" void kernel_launch(void* const* d_in, const int* in_sizes, int n_in,
                              void* d_out, int out_size) {
    const float* rois      = (const float*)d_in[0];
    const float* bbox_pred = (const float*)d_in[1];
    const float* scores    = (const float*)d_in[2];
    const float* im_info   = (const float*)d_in[3];
    const float* feats     = (const float*)d_in[4];
    float* out = (float*)d_out;

    nms_fused_kernel<<<BB * CF, 512>>>(rois, bbox_pred, scores, im_info, out);
    feats_kernel<<<BB * NN / 8, 256>>>((const float4*)feats, out);
}